// round 1
// baseline (speedup 1.0000x reference)
#include <cuda_runtime.h>
#include <cstdint>

#define NN 100000
#define NE 3200000
#define NG 64

// ---------------- persistent scratch (__device__ globals: allowed) ----------------
__device__ int g_e64, g_b64;
__device__ int g_src32[NE];
__device__ int g_dst32[NE];
__device__ int g_batch32[NN];
__device__ int g_count[NN];
__device__ int g_off[NN + 1];
__device__ int g_cursor[NN];
__device__ int g_adj[NE];
__device__ int g_bsum[128];
__device__ __align__(16) float g_h1[NN * 16];
__device__ __align__(16) float g_as1[NN * 4];
__device__ __align__(16) float g_ad1[NN * 4];
__device__ __align__(16) float g_h2w[NN * 32];
__device__ float g_as2[NN];
__device__ float g_ad2[NN];
__device__ __align__(16) float g_pool[NG * 32];
__device__ float g_cnt[NG];

__device__ __forceinline__ float lrelu(float x) { return x > 0.f ? x : 0.2f * x; }
__device__ __forceinline__ float mishf(float x) {
    float sp = log1pf(__expf(x));
    return x * tanhf(sp);
}

// ---------------- dtype detection: are edge_index / batch int64 or int32? --------
// int64 values < 2^31 -> every odd 32-bit word (high half) is zero.
__global__ void detect_kernel(const int* __restrict__ ei, const int* __restrict__ bt) {
    int t = threadIdx.x;
    int lane = t & 31;
    if (t < 32) {
        int v = ei[2 * lane + 1];  // random edge values if int32 data; high halves if int64
        unsigned any = __ballot_sync(0xffffffffu, v != 0);
        if (lane == 0) g_e64 = (any == 0u) ? 1 : 0;
    } else if (t < 64) {
        // batch is sorted ascending to 63; tail values nonzero if int32 data.
        int v = bt[99999 - 2 * lane];  // odd indices, within first NN words (safe both ways)
        unsigned any = __ballot_sync(0xffffffffu, v != 0);
        if (lane == 0) g_b64 = (any == 0u) ? 1 : 0;
    }
}

// ---------------- zero init ----------------
__global__ void zero_kernel() {
    int i = blockIdx.x * 256 + threadIdx.x;
    if (i < NN) g_count[i] = 0;
    if (i < NG * 32) g_pool[i] = 0.f;
    if (i < NG) g_cnt[i] = 0.f;
}

// ---------------- convert edges to int32 + histogram over dst ----------------
__global__ void conv_edges_kernel(const void* __restrict__ ep) {
    int e = blockIdx.x * 256 + threadIdx.x;
    if (e >= NE) return;
    int s, d;
    if (g_e64) {
        const long long* p = (const long long*)ep;
        s = (int)p[e];
        d = (int)p[NE + e];
    } else {
        const int* p = (const int*)ep;
        s = p[e];
        d = p[NE + e];
    }
    g_src32[e] = s;
    g_dst32[e] = d;
    atomicAdd(&g_count[d], 1);
}

// ---------------- convert batch + warp-aggregated graph node counts ----------------
__global__ void conv_batch_kernel(const void* __restrict__ bp) {
    int i = blockIdx.x * 256 + threadIdx.x;
    int gid = -1;
    if (i < NN) {
        gid = g_b64 ? (int)((const long long*)bp)[i] : ((const int*)bp)[i];
        g_batch32[i] = gid;
    }
    unsigned mask = __match_any_sync(0xffffffffu, gid);
    int lane = threadIdx.x & 31;
    if (gid >= 0 && (int)(__ffs(mask) - 1) == lane)
        atomicAdd(&g_cnt[gid], (float)__popc(mask));
}

// ---------------- scan (3 kernels): exclusive prefix of g_count -> g_off ----------
__global__ void scan_a_kernel() {
    __shared__ int s[1024];
    int t = threadIdx.x;
    int i = blockIdx.x * 1024 + t;
    int c = (i < NN) ? g_count[i] : 0;
    s[t] = c;
    __syncthreads();
    for (int d = 1; d < 1024; d <<= 1) {
        int v = (t >= d) ? s[t - d] : 0;
        __syncthreads();
        s[t] += v;
        __syncthreads();
    }
    if (i < NN) g_off[i] = s[t];  // inclusive within chunk (temp)
    if (t == 1023) g_bsum[blockIdx.x] = s[1023];
}
__global__ void scan_b_kernel() {
    __shared__ int s[128];
    int t = threadIdx.x;
    int nb = (NN + 1023) / 1024;  // 98
    int v = (t < nb) ? g_bsum[t] : 0;
    s[t] = v;
    __syncthreads();
    for (int d = 1; d < 128; d <<= 1) {
        int u = (t >= d) ? s[t - d] : 0;
        __syncthreads();
        s[t] += u;
        __syncthreads();
    }
    g_bsum[t] = s[t];  // inclusive scan of block sums
}
__global__ void scan_c_kernel() {
    int i = blockIdx.x * 256 + threadIdx.x;
    if (i < NN) {
        int blk = i >> 10;
        int add = blk ? g_bsum[blk - 1] : 0;
        int ex = g_off[i] - g_count[i] + add;  // exclusive global
        g_off[i] = ex;
        g_cursor[i] = ex;
    }
    if (i == 0) g_off[NN] = NE;
}

// ---------------- scatter: build CSR adjacency (src grouped by dst) ----------------
__global__ void scatter_kernel() {
    int e = blockIdx.x * 256 + threadIdx.x;
    if (e >= NE) return;
    int d = g_dst32[e];
    int pos = atomicAdd(&g_cursor[d], 1);
    g_adj[pos] = g_src32[e];
}

// ---------------- GEMM1: h1 = x @ W1 ; alpha_src1/alpha_dst1 per (node, head) -----
// block 128 threads, 16 nodes per block. thread t: j = t%16 (output col), n0 = t/16.
__global__ void gemm1_kernel(const float* __restrict__ x, const float* __restrict__ W1,
                             const float* __restrict__ a_src1, const float* __restrict__ a_dst1) {
    __shared__ float WsT[16 * 132];  // transposed W1, padded rows (2-way max conflicts)
    __shared__ float xs[16 * 132];   // 16 x-rows, padded
    int t = threadIdx.x;
    for (int i = t; i < 2048; i += 128) {
        int j = i >> 7, k = i & 127;
        WsT[j * 132 + k] = W1[k * 16 + j];
    }
    int j = t & 15;
    int n0 = t >> 4;  // 0..7
    float asj = a_src1[j], adj_ = a_dst1[j];
    __syncthreads();

    int nb = blockIdx.x * 16;
    const float4* xg = reinterpret_cast<const float4*>(x + (size_t)nb * 128);
    for (int i = t; i < 512; i += 128) {
        int row = i >> 5, c4 = i & 31;
        reinterpret_cast<float4*>(xs + row * 132)[c4] = xg[i];
    }
    __syncthreads();

    const float4* wrow = reinterpret_cast<const float4*>(WsT + j * 132);
    const float4* xrA = reinterpret_cast<const float4*>(xs + n0 * 132);
    const float4* xrB = reinterpret_cast<const float4*>(xs + (n0 + 8) * 132);
    float accA = 0.f, accB = 0.f;
#pragma unroll
    for (int k4 = 0; k4 < 32; k4++) {
        float4 w = wrow[k4];
        float4 xa = xrA[k4];
        float4 xb = xrB[k4];
        accA = fmaf(xa.x, w.x, accA); accA = fmaf(xa.y, w.y, accA);
        accA = fmaf(xa.z, w.z, accA); accA = fmaf(xa.w, w.w, accA);
        accB = fmaf(xb.x, w.x, accB); accB = fmaf(xb.y, w.y, accB);
        accB = fmaf(xb.z, w.z, accB); accB = fmaf(xb.w, w.w, accB);
    }
    int nA = nb + n0, nB = nb + n0 + 8;
    g_h1[nA * 16 + j] = accA;
    g_h1[nB * 16 + j] = accB;
    float sA = accA * asj, dA = accA * adj_;
    float sB = accB * asj, dB = accB * adj_;
    sA += __shfl_xor_sync(0xffffffffu, sA, 1); sA += __shfl_xor_sync(0xffffffffu, sA, 2);
    dA += __shfl_xor_sync(0xffffffffu, dA, 1); dA += __shfl_xor_sync(0xffffffffu, dA, 2);
    sB += __shfl_xor_sync(0xffffffffu, sB, 1); sB += __shfl_xor_sync(0xffffffffu, sB, 2);
    dB += __shfl_xor_sync(0xffffffffu, dB, 1); dB += __shfl_xor_sync(0xffffffffu, dB, 2);
    if ((j & 3) == 0) {
        int h = j >> 2;
        g_as1[nA * 4 + h] = sA; g_ad1[nA * 4 + h] = dA;
        g_as1[nB * 4 + h] = sB; g_ad1[nB * 4 + h] = dB;
    }
}

// ---------------- Layer 1: warp per dst node; 8 edge-groups x 4 lanes (one lane/head)
// Fused: online softmax aggregate -> +b1 -> mish -> z@W2 -> alpha_src2/alpha_dst2.
__global__ void l1_edge_kernel(const float* __restrict__ b1, const float* __restrict__ W2,
                               const float* __restrict__ a_src2, const float* __restrict__ a_dst2) {
    __shared__ float W2s[512];
    int tid = threadIdx.x;
    for (int i = tid; i < 512; i += 256) W2s[i] = W2[i];
    __syncthreads();
    int lane = tid & 31;
    int n = blockIdx.x * 8 + (tid >> 5);
    int g = lane >> 2, r = lane & 3;  // group, head
    float adv = g_ad1[n * 4 + r];
    int start = g_off[n], end = g_off[n + 1];

    float m, den;
    float a0, a1, a2, a3;
    if (g == 0) {  // self loop (src = n)
        float e = lrelu(g_as1[n * 4 + r] + adv);
        m = e; den = 1.f;
        float4 hv = *reinterpret_cast<const float4*>(&g_h1[n * 16 + r * 4]);
        a0 = hv.x; a1 = hv.y; a2 = hv.z; a3 = hv.w;
    } else {
        m = -1e30f; den = 0.f;
        a0 = a1 = a2 = a3 = 0.f;
    }
    for (int idx = start + g; idx < end; idx += 8) {
        int src = g_adj[idx];
        float e = lrelu(g_as1[src * 4 + r] + adv);
        float4 hv = *reinterpret_cast<const float4*>(&g_h1[src * 16 + r * 4]);
        float mn = fmaxf(m, e);
        float sc = __expf(m - mn);
        float p = __expf(e - mn);
        den = den * sc + p;
        a0 = a0 * sc + p * hv.x;
        a1 = a1 * sc + p * hv.y;
        a2 = a2 * sc + p * hv.z;
        a3 = a3 * sc + p * hv.w;
        m = mn;
    }
    // combine the 8 groups (same head r)
#pragma unroll
    for (int o = 4; o < 32; o <<= 1) {
        float m2 = __shfl_xor_sync(0xffffffffu, m, o);
        float d2 = __shfl_xor_sync(0xffffffffu, den, o);
        float b0 = __shfl_xor_sync(0xffffffffu, a0, o);
        float b1_ = __shfl_xor_sync(0xffffffffu, a1, o);
        float b2_ = __shfl_xor_sync(0xffffffffu, a2, o);
        float b3 = __shfl_xor_sync(0xffffffffu, a3, o);
        float M = fmaxf(m, m2);
        float s1 = __expf(m - M), s2 = __expf(m2 - M);
        den = den * s1 + d2 * s2;
        a0 = a0 * s1 + b0 * s2;
        a1 = a1 * s1 + b1_ * s2;
        a2 = a2 * s1 + b2_ * s2;
        a3 = a3 * s1 + b3 * s2;
        m = M;
    }
    float inv = 1.f / den;
    // z channels r*4 .. r*4+3 (flat = head*4 + c), + bias, mish
    float z0 = mishf(fmaf(a0, inv, 0.f) + b1[r * 4 + 0]);
    float z1 = mishf(fmaf(a1, inv, 0.f) + b1[r * 4 + 1]);
    float z2 = mishf(fmaf(a2, inv, 0.f) + b1[r * 4 + 2]);
    float z3 = mishf(fmaf(a3, inv, 0.f) + b1[r * 4 + 3]);
    // hh2[lane] = sum_k z[k] * W2[k][lane]  (z broadcast from lanes 0..3)
    float hh = 0.f;
#pragma unroll
    for (int s = 0; s < 4; s++) {
        float y0 = __shfl_sync(0xffffffffu, z0, s);
        float y1 = __shfl_sync(0xffffffffu, z1, s);
        float y2 = __shfl_sync(0xffffffffu, z2, s);
        float y3 = __shfl_sync(0xffffffffu, z3, s);
        const float* wk = &W2s[(s * 4) * 32 + lane];
        hh = fmaf(y0, wk[0], hh);
        hh = fmaf(y1, wk[32], hh);
        hh = fmaf(y2, wk[64], hh);
        hh = fmaf(y3, wk[96], hh);
    }
    g_h2w[n * 32 + lane] = hh;
    float ss = hh * a_src2[lane];
    float dd = hh * a_dst2[lane];
#pragma unroll
    for (int o = 16; o >= 1; o >>= 1) {
        ss += __shfl_xor_sync(0xffffffffu, ss, o);
        dd += __shfl_xor_sync(0xffffffffu, dd, o);
    }
    if (lane == 0) {
        g_as2[n] = ss;
        g_ad2[n] = dd;
    }
}

// ---------------- Layer 2: warp per dst node; 4 edge-groups x 8 lanes --------------
// Fused: online softmax -> +b2 -> mish -> mean-pool atomics.
__global__ void l2_edge_kernel(const float* __restrict__ b2) {
    int tid = threadIdx.x;
    int lane = tid & 31;
    int n = blockIdx.x * 8 + (tid >> 5);
    int g = lane >> 3, r = lane & 7;  // group, channel-quad
    float adv = g_ad2[n];
    int start = g_off[n], end = g_off[n + 1];

    float m, den;
    float a0, a1, a2, a3;
    if (g == 0) {  // self loop
        float e = lrelu(g_as2[n] + adv);
        m = e; den = 1.f;
        float4 hv = *reinterpret_cast<const float4*>(&g_h2w[n * 32 + r * 4]);
        a0 = hv.x; a1 = hv.y; a2 = hv.z; a3 = hv.w;
    } else {
        m = -1e30f; den = 0.f;
        a0 = a1 = a2 = a3 = 0.f;
    }
    for (int idx = start + g; idx < end; idx += 4) {
        int src = g_adj[idx];
        float e = lrelu(g_as2[src] + adv);
        float4 hv = *reinterpret_cast<const float4*>(&g_h2w[src * 32 + r * 4]);
        float mn = fmaxf(m, e);
        float sc = __expf(m - mn);
        float p = __expf(e - mn);
        den = den * sc + p;
        a0 = a0 * sc + p * hv.x;
        a1 = a1 * sc + p * hv.y;
        a2 = a2 * sc + p * hv.z;
        a3 = a3 * sc + p * hv.w;
        m = mn;
    }
#pragma unroll
    for (int o = 8; o < 32; o <<= 1) {
        float m2 = __shfl_xor_sync(0xffffffffu, m, o);
        float d2 = __shfl_xor_sync(0xffffffffu, den, o);
        float c0 = __shfl_xor_sync(0xffffffffu, a0, o);
        float c1 = __shfl_xor_sync(0xffffffffu, a1, o);
        float c2 = __shfl_xor_sync(0xffffffffu, a2, o);
        float c3 = __shfl_xor_sync(0xffffffffu, a3, o);
        float M = fmaxf(m, m2);
        float s1 = __expf(m - M), s2 = __expf(m2 - M);
        den = den * s1 + d2 * s2;
        a0 = a0 * s1 + c0 * s2;
        a1 = a1 * s1 + c1 * s2;
        a2 = a2 * s1 + c2 * s2;
        a3 = a3 * s1 + c3 * s2;
        m = M;
    }
    if (g == 0) {
        float inv = 1.f / den;
        float y0 = mishf(a0 * inv + b2[r * 4 + 0]);
        float y1 = mishf(a1 * inv + b2[r * 4 + 1]);
        float y2 = mishf(a2 * inv + b2[r * 4 + 2]);
        float y3 = mishf(a3 * inv + b2[r * 4 + 3]);
        int gid = g_batch32[n];
        float* p = &g_pool[gid * 32 + r * 4];
        atomicAdd(p + 0, y0);
        atomicAdd(p + 1, y1);
        atomicAdd(p + 2, y2);
        atomicAdd(p + 3, y3);
    }
}

// ---------------- finalize: mean pool ----------------
__global__ void finalize_kernel(float* __restrict__ out) {
    int i = blockIdx.x * 256 + threadIdx.x;
    if (i < NG * 32) out[i] = g_pool[i] / fmaxf(g_cnt[i >> 5], 1.f);
}

extern "C" void kernel_launch(void* const* d_in, const int* in_sizes, int n_in,
                              void* d_out, int out_size) {
    const float* x = (const float*)d_in[0];
    const void* ei = d_in[1];
    const void* bt = d_in[2];
    const float* W1 = (const float*)d_in[3];
    const float* b1 = (const float*)d_in[4];
    const float* a_src1 = (const float*)d_in[5];
    const float* a_dst1 = (const float*)d_in[6];
    const float* W2 = (const float*)d_in[7];
    const float* b2 = (const float*)d_in[8];
    const float* a_src2 = (const float*)d_in[9];
    const float* a_dst2 = (const float*)d_in[10];
    float* out = (float*)d_out;

    detect_kernel<<<1, 64>>>((const int*)ei, (const int*)bt);
    zero_kernel<<<(NN + 255) / 256, 256>>>();
    conv_edges_kernel<<<(NE + 255) / 256, 256>>>(ei);
    conv_batch_kernel<<<(NN + 255) / 256, 256>>>(bt);
    scan_a_kernel<<<(NN + 1023) / 1024, 1024>>>();
    scan_b_kernel<<<1, 128>>>();
    scan_c_kernel<<<(NN + 256) / 256, 256>>>();
    scatter_kernel<<<(NE + 255) / 256, 256>>>();
    gemm1_kernel<<<NN / 16, 128>>>(x, W1, a_src1, a_dst1);
    l1_edge_kernel<<<NN / 8, 256>>>(b1, W2, a_src2, a_dst2);
    l2_edge_kernel<<<NN / 8, 256>>>(b2);
    finalize_kernel<<<8, 256>>>(out);
}

// round 3
// speedup vs baseline: 2.4689x; 2.4689x over previous
#include <cuda_runtime.h>

#define NN 100000
#define NE 3200000
#define NG 64

// ---------------- persistent scratch ----------------
__device__ int g_e64, g_b64;
__device__ int g_src32[NE];
__device__ int g_dst32[NE];
__device__ int g_batch32[NN];
__device__ int g_count[NN];
__device__ int g_off[NN + 1];
__device__ int g_cursor[NN];
__device__ int g_adj[NE];
__device__ int g_bsum[128];
__device__ __align__(16) float g_h1[NN * 16];
__device__ __align__(16) float g_as1[NN * 4];
__device__ __align__(16) float g_ad1[NN * 4];
__device__ __align__(16) float g_h2w[NN * 32];
__device__ float g_as2[NN];
__device__ float g_ad2[NN];
__device__ float g_pool[NG * 32];
__device__ float g_cnt[NG];

__device__ __forceinline__ float lrelu(float x) { return x > 0.f ? x : 0.2f * x; }
__device__ __forceinline__ float mishf(float x) {
    float sp = log1pf(__expf(x));
    return x * tanhf(sp);
}

// ---------------- zero init + dtype detect (block 0) ----------------
__global__ void zero_detect_kernel(const int* __restrict__ ei, const int* __restrict__ bt) {
    int i = blockIdx.x * 256 + threadIdx.x;
    if (i < NN) g_count[i] = 0;
    if (i < NG * 32) g_pool[i] = 0.f;
    if (i < NG) g_cnt[i] = 0.f;
    if (blockIdx.x == 0) {
        int t = threadIdx.x, lane = t & 31;
        if (t < 32) {
            int v = ei[2 * lane + 1];
            unsigned any = __ballot_sync(0xffffffffu, v != 0);
            if (lane == 0) g_e64 = (any == 0u) ? 1 : 0;
        } else if (t < 64) {
            int v = bt[99999 - 2 * lane];
            unsigned any = __ballot_sync(0xffffffffu, v != 0);
            if (lane == 0) g_b64 = (any == 0u) ? 1 : 0;
        }
    }
}

// ---------------- fused: convert edges (+hist) and batch (+counts) ----------------
__global__ void conv_kernel(const void* __restrict__ ep, const void* __restrict__ bp) {
    int e = blockIdx.x * 256 + threadIdx.x;
    int lane = threadIdx.x & 31;
    if (e < NE) {
        int s, d;
        if (g_e64) {
            const long long* p = (const long long*)ep;
            s = (int)p[e];
            d = (int)p[NE + e];
        } else {
            const int* p = (const int*)ep;
            s = p[e];
            d = p[NE + e];
        }
        g_src32[e] = s;
        g_dst32[e] = d;
        atomicAdd(&g_count[d], 1);
    }
    int gid = -1;
    if (e < NN) {
        gid = g_b64 ? (int)((const long long*)bp)[e] : ((const int*)bp)[e];
        g_batch32[e] = gid;
    }
    unsigned mask = __match_any_sync(0xffffffffu, gid);
    if (gid >= 0 && (int)(__ffs(mask) - 1) == lane)
        atomicAdd(&g_cnt[gid], (float)__popc(mask));
}

// ---------------- scan (3 kernels) ----------------
__global__ void scan_a_kernel() {
    __shared__ int s[1024];
    int t = threadIdx.x;
    int i = blockIdx.x * 1024 + t;
    int c = (i < NN) ? g_count[i] : 0;
    s[t] = c;
    __syncthreads();
    for (int d = 1; d < 1024; d <<= 1) {
        int v = (t >= d) ? s[t - d] : 0;
        __syncthreads();
        s[t] += v;
        __syncthreads();
    }
    if (i < NN) g_off[i] = s[t];
    if (t == 1023) g_bsum[blockIdx.x] = s[1023];
}
__global__ void scan_b_kernel() {
    __shared__ int s[128];
    int t = threadIdx.x;
    int nb = (NN + 1023) / 1024;
    int v = (t < nb) ? g_bsum[t] : 0;
    s[t] = v;
    __syncthreads();
    for (int d = 1; d < 128; d <<= 1) {
        int u = (t >= d) ? s[t - d] : 0;
        __syncthreads();
        s[t] += u;
        __syncthreads();
    }
    g_bsum[t] = s[t];
}
__global__ void scan_c_kernel() {
    int i = blockIdx.x * 256 + threadIdx.x;
    if (i < NN) {
        int blk = i >> 10;
        int add = blk ? g_bsum[blk - 1] : 0;
        int ex = g_off[i] - g_count[i] + add;
        g_off[i] = ex;
        g_cursor[i] = ex;
    }
    if (i == 0) g_off[NN] = NE;
}

// ---------------- scatter: build CSR adjacency ----------------
__global__ void scatter_kernel() {
    int e = blockIdx.x * 256 + threadIdx.x;
    if (e >= NE) return;
    int d = g_dst32[e];
    int pos = atomicAdd(&g_cursor[d], 1);
    g_adj[pos] = g_src32[e];
}

// ---------------- GEMM1: h1 = x @ W1 ; per-(node,head) logits ----------------
__global__ void gemm1_kernel(const float* __restrict__ x, const float* __restrict__ W1,
                             const float* __restrict__ a_src1, const float* __restrict__ a_dst1) {
    __shared__ float WsT[16 * 132];
    __shared__ float xs[16 * 132];
    int t = threadIdx.x;
    for (int i = t; i < 2048; i += 128) {
        int j = i >> 7, k = i & 127;
        WsT[j * 132 + k] = W1[k * 16 + j];
    }
    int j = t & 15;
    int n0 = t >> 4;
    float asj = a_src1[j], adj_ = a_dst1[j];
    __syncthreads();

    int nb = blockIdx.x * 16;
    const float4* xg = reinterpret_cast<const float4*>(x + (size_t)nb * 128);
    for (int i = t; i < 512; i += 128) {
        int row = i >> 5, c4 = i & 31;
        reinterpret_cast<float4*>(xs + row * 132)[c4] = xg[i];
    }
    __syncthreads();

    const float4* wrow = reinterpret_cast<const float4*>(WsT + j * 132);
    const float4* xrA = reinterpret_cast<const float4*>(xs + n0 * 132);
    const float4* xrB = reinterpret_cast<const float4*>(xs + (n0 + 8) * 132);
    float accA = 0.f, accB = 0.f;
#pragma unroll
    for (int k4 = 0; k4 < 32; k4++) {
        float4 w = wrow[k4];
        float4 xa = xrA[k4];
        float4 xb = xrB[k4];
        accA = fmaf(xa.x, w.x, accA); accA = fmaf(xa.y, w.y, accA);
        accA = fmaf(xa.z, w.z, accA); accA = fmaf(xa.w, w.w, accA);
        accB = fmaf(xb.x, w.x, accB); accB = fmaf(xb.y, w.y, accB);
        accB = fmaf(xb.z, w.z, accB); accB = fmaf(xb.w, w.w, accB);
    }
    int nA = nb + n0, nB = nb + n0 + 8;
    g_h1[nA * 16 + j] = accA;
    g_h1[nB * 16 + j] = accB;
    float sA = accA * asj, dA = accA * adj_;
    float sB = accB * asj, dB = accB * adj_;
    sA += __shfl_xor_sync(0xffffffffu, sA, 1); sA += __shfl_xor_sync(0xffffffffu, sA, 2);
    dA += __shfl_xor_sync(0xffffffffu, dA, 1); dA += __shfl_xor_sync(0xffffffffu, dA, 2);
    sB += __shfl_xor_sync(0xffffffffu, sB, 1); sB += __shfl_xor_sync(0xffffffffu, sB, 2);
    dB += __shfl_xor_sync(0xffffffffu, dB, 1); dB += __shfl_xor_sync(0xffffffffu, dB, 2);
    if ((j & 3) == 0) {
        int h = j >> 2;
        g_as1[nA * 4 + h] = sA; g_ad1[nA * 4 + h] = dA;
        g_as1[nB * 4 + h] = sB; g_ad1[nB * 4 + h] = dB;
    }
}

// ---------------- Layer 1: warp/node, 8 groups x 4 lanes, NO-MAX softmax ----------
__global__ void l1_edge_kernel(const float* __restrict__ b1, const float* __restrict__ W2,
                               const float* __restrict__ a_src2, const float* __restrict__ a_dst2) {
    __shared__ float W2s[512];
    int tid = threadIdx.x;
    for (int i = tid; i < 512; i += 256) W2s[i] = W2[i];
    __syncthreads();
    int lane = tid & 31;
    int n = blockIdx.x * 8 + (tid >> 5);
    int g = lane >> 2, r = lane & 3;
    float adv = g_ad1[n * 4 + r];
    int start = g_off[n], end = g_off[n + 1];

    float den, a0, a1, a2, a3;
    if (g == 0) {  // self loop
        float p = __expf(lrelu(g_as1[n * 4 + r] + adv));
        float4 hv = *reinterpret_cast<const float4*>(&g_h1[n * 16 + r * 4]);
        den = p;
        a0 = p * hv.x; a1 = p * hv.y; a2 = p * hv.z; a3 = p * hv.w;
    } else {
        den = 0.f; a0 = a1 = a2 = a3 = 0.f;
    }
    int idx = start + g;
    int src = (idx < end) ? g_adj[idx] : -1;
    while (src >= 0) {
        idx += 8;
        int nsrc = (idx < end) ? g_adj[idx] : -1;  // prefetch next index
        float e = lrelu(g_as1[src * 4 + r] + adv);
        float4 hv = *reinterpret_cast<const float4*>(&g_h1[src * 16 + r * 4]);
        float p = __expf(e);
        den += p;
        a0 = fmaf(p, hv.x, a0);
        a1 = fmaf(p, hv.y, a1);
        a2 = fmaf(p, hv.z, a2);
        a3 = fmaf(p, hv.w, a3);
        src = nsrc;
    }
#pragma unroll
    for (int o = 4; o < 32; o <<= 1) {
        den += __shfl_xor_sync(0xffffffffu, den, o);
        a0 += __shfl_xor_sync(0xffffffffu, a0, o);
        a1 += __shfl_xor_sync(0xffffffffu, a1, o);
        a2 += __shfl_xor_sync(0xffffffffu, a2, o);
        a3 += __shfl_xor_sync(0xffffffffu, a3, o);
    }
    float inv = 1.f / den;
    // lane k<16 computes z for flat channel c = (k&3)*4 + (k>>2)
    float z = 0.f;
    if (lane < 16) {
        int j = lane >> 2;
        float av = (j == 0) ? a0 : (j == 1) ? a1 : (j == 2) ? a2 : a3;
        z = mishf(av * inv + b1[r * 4 + j]);
    }
    float hh = 0.f;
#pragma unroll
    for (int k = 0; k < 16; k++) {
        int c = (k & 3) * 4 + (k >> 2);
        float zk = __shfl_sync(0xffffffffu, z, k);
        hh = fmaf(zk, W2s[c * 32 + lane], hh);
    }
    g_h2w[n * 32 + lane] = hh;
    float ss = hh * a_src2[lane];
    float dd = hh * a_dst2[lane];
#pragma unroll
    for (int o = 16; o >= 1; o >>= 1) {
        ss += __shfl_xor_sync(0xffffffffu, ss, o);
        dd += __shfl_xor_sync(0xffffffffu, dd, o);
    }
    if (lane == 0) {
        g_as2[n] = ss;
        g_ad2[n] = dd;
    }
}

// ---------------- Layer 2: warp/node, 8 groups x 4 lanes (8 ch each), NO-MAX ------
__global__ void l2_edge_kernel(const float* __restrict__ b2) {
    __shared__ float spool[8 * 32];
    __shared__ int sgid[8];
    int tid = threadIdx.x, lane = tid & 31, w = tid >> 5;
    int n = blockIdx.x * 8 + w;
    int g = lane >> 2, r = lane & 3;
    float adv = g_ad2[n];
    int start = g_off[n], end = g_off[n + 1];

    float den;
    float ac[8];
    if (g == 0) {  // self loop
        float p = __expf(lrelu(g_as2[n] + adv));
        const float4* hp = reinterpret_cast<const float4*>(&g_h2w[n * 32 + r * 8]);
        float4 h0 = hp[0], h1v = hp[1];
        den = p;
        ac[0] = p * h0.x;  ac[1] = p * h0.y;  ac[2] = p * h0.z;  ac[3] = p * h0.w;
        ac[4] = p * h1v.x; ac[5] = p * h1v.y; ac[6] = p * h1v.z; ac[7] = p * h1v.w;
    } else {
        den = 0.f;
#pragma unroll
        for (int c = 0; c < 8; c++) ac[c] = 0.f;
    }
    int idx = start + g;
    int src = (idx < end) ? g_adj[idx] : -1;
    while (src >= 0) {
        idx += 8;
        int nsrc = (idx < end) ? g_adj[idx] : -1;  // prefetch
        float e = lrelu(g_as2[src] + adv);
        const float4* hp = reinterpret_cast<const float4*>(&g_h2w[src * 32 + r * 8]);
        float4 h0 = hp[0], h1v = hp[1];
        float p = __expf(e);
        den += p;
        ac[0] = fmaf(p, h0.x, ac[0]);  ac[1] = fmaf(p, h0.y, ac[1]);
        ac[2] = fmaf(p, h0.z, ac[2]);  ac[3] = fmaf(p, h0.w, ac[3]);
        ac[4] = fmaf(p, h1v.x, ac[4]); ac[5] = fmaf(p, h1v.y, ac[5]);
        ac[6] = fmaf(p, h1v.z, ac[6]); ac[7] = fmaf(p, h1v.w, ac[7]);
        src = nsrc;
    }
#pragma unroll
    for (int o = 4; o < 32; o <<= 1) {
        den += __shfl_xor_sync(0xffffffffu, den, o);
#pragma unroll
        for (int c = 0; c < 8; c++) ac[c] += __shfl_xor_sync(0xffffffffu, ac[c], o);
    }
    if (g == 0) {
        float inv = 1.f / den;
#pragma unroll
        for (int c = 0; c < 8; c++)
            spool[w * 32 + r * 8 + c] = mishf(ac[c] * inv + b2[r * 8 + c]);
        if (lane == 0) sgid[w] = g_batch32[n];
    }
    __syncthreads();
    if (w == 0) {  // block-aggregated pool atomics: lane = channel
        float acc = 0.f;
        int cur = sgid[0];
        for (int row = 0; row < 8; row++) {
            int gid2 = sgid[row];
            if (gid2 != cur) {
                atomicAdd(&g_pool[cur * 32 + lane], acc);
                acc = 0.f;
                cur = gid2;
            }
            acc += spool[row * 32 + lane];
        }
        atomicAdd(&g_pool[cur * 32 + lane], acc);
    }
}

// ---------------- finalize: mean pool ----------------
__global__ void finalize_kernel(float* __restrict__ out) {
    int i = blockIdx.x * 256 + threadIdx.x;
    if (i < NG * 32) out[i] = g_pool[i] / fmaxf(g_cnt[i >> 5], 1.f);
}

extern "C" void kernel_launch(void* const* d_in, const int* in_sizes, int n_in,
                              void* d_out, int out_size) {
    const float* x = (const float*)d_in[0];
    const void* ei = d_in[1];
    const void* bt = d_in[2];
    const float* W1 = (const float*)d_in[3];
    const float* b1 = (const float*)d_in[4];
    const float* a_src1 = (const float*)d_in[5];
    const float* a_dst1 = (const float*)d_in[6];
    const float* W2 = (const float*)d_in[7];
    const float* b2 = (const float*)d_in[8];
    const float* a_src2 = (const float*)d_in[9];
    const float* a_dst2 = (const float*)d_in[10];
    float* out = (float*)d_out;

    zero_detect_kernel<<<(NN + 255) / 256, 256>>>((const int*)ei, (const int*)bt);
    conv_kernel<<<(NE + 255) / 256, 256>>>(ei, bt);
    scan_a_kernel<<<(NN + 1023) / 1024, 1024>>>();
    gemm1_kernel<<<NN / 16, 128>>>(x, W1, a_src1, a_dst1);
    scan_b_kernel<<<1, 128>>>();
    scan_c_kernel<<<(NN + 255) / 256, 256>>>();
    scatter_kernel<<<(NE + 255) / 256, 256>>>();
    l1_edge_kernel<<<NN / 8, 256>>>(b1, W2, a_src2, a_dst2);
    l2_edge_kernel<<<NN / 8, 256>>>(b2);
    finalize_kernel<<<8, 256>>>(out);
}